// round 1
// baseline (speedup 1.0000x reference)
#include <cuda_runtime.h>
#include <cuda_bf16.h>
#include <cstdint>

// Problem constants
constexpr int BATCH  = 32;
constexpr int HIDDEN = 4096;
constexpr int NHEAD  = 32;
constexpr int NKV    = 8;
constexpr int HD     = 128;
constexpr int GRP    = 4;      // NHEAD / NKV
constexpr int MAXBLK = 64;
constexpr int NSLOT  = 65536;  // NUM_BLOCKS * BLOCK_SIZE
constexpr int NSPLIT = 8;      // KV splits (1 warp each, 128 positions)

// Scratch (no allocations allowed -> __device__ globals)
__device__ float g_q[BATCH * NHEAD * HD];
__device__ float g_k[BATCH * NKV * HD];
__device__ float g_v[BATCH * NKV * HD];
__device__ float g_attn[BATCH * NHEAD * HD];
__device__ float g_part[BATCH * NKV * NSPLIT * GRP * HD];
__device__ float g_pm[BATCH * NKV * NSPLIT * GRP];
__device__ float g_pl[BATCH * NKV * NSPLIT * GRP];
__device__ int   g_inv[NSLOT];

// ---------------------------------------------------------------------------
// f32x2 packed FMA helpers (2x fp32 FMA throughput vs FFMA 3-reg on sm_103a)
// ---------------------------------------------------------------------------
__device__ __forceinline__ void ffma2(unsigned long long& d, unsigned long long a,
                                      unsigned long long b) {
    asm("fma.rn.f32x2 %0, %1, %2, %0;" : "+l"(d) : "l"(a), "l"(b));
}
__device__ __forceinline__ unsigned long long pack2(float x) {
    unsigned long long r;
    asm("mov.b64 %0, {%1, %1};" : "=l"(r) : "f"(x));
    return r;
}

// ---------------------------------------------------------------------------
// GEMM: C[32, N] = A[32, 4096] * W[N, 4096]^T   (fp32, f32x2 inner)
// Block: 32 output columns. 256 threads = 32 slots (8 n-grp x 4 b-grp) x 8 k-slices.
// Per-thread tile: 4 n x 8 b (as 4 f32x2 pairs). Shared k-chunk = 64.
// ---------------------------------------------------------------------------
__global__ void __launch_bounds__(256, 2)
gemm32(const float* __restrict__ A, const float* __restrict__ W,
       float* __restrict__ C, int ldc)
{
    __shared__ __align__(16) float smem[8 * 32 * 34];          // 34816 B
    float (*sA)[36] = reinterpret_cast<float(*)[36]>(smem);    // [64][36]
    float (*sW)[36] = reinterpret_cast<float(*)[36]>(smem + 64 * 36);

    const int tid   = threadIdx.x;
    const int slot  = tid & 31;
    const int slice = tid >> 5;
    const int ng    = slot & 7;
    const int bg    = slot >> 3;
    const int nl    = ng * 4;
    const int b0    = bg * 8;
    const int n0    = blockIdx.x * 32;

    unsigned long long acc[4][4];
#pragma unroll
    for (int i = 0; i < 4; i++)
#pragma unroll
        for (int j = 0; j < 4; j++) acc[i][j] = 0ull;

    for (int c = 0; c < HIDDEN; c += 64) {
#pragma unroll
        for (int i = 0; i < 8; i++) {
            int idx = tid + i * 256;
            int kL = idx & 63, bb = idx >> 6;
            sA[kL][bb] = A[bb * HIDDEN + c + kL];
        }
#pragma unroll
        for (int i = 0; i < 8; i++) {
            int idx = tid + i * 256;
            int kL = idx & 63, nn = idx >> 6;
            sW[kL][nn] = W[(size_t)(n0 + nn) * HIDDEN + c + kL];
        }
        __syncthreads();
#pragma unroll
        for (int u = 0; u < 8; u++) {
            int kk = slice * 8 + u;
            float4 w4 = *(const float4*)&sW[kk][nl];
            ulonglong2 aA = *(const ulonglong2*)&sA[kk][b0];
            ulonglong2 aB = *(const ulonglong2*)&sA[kk][b0 + 4];
            unsigned long long w0 = pack2(w4.x), w1 = pack2(w4.y);
            unsigned long long w2 = pack2(w4.z), w3 = pack2(w4.w);
            ffma2(acc[0][0], w0, aA.x); ffma2(acc[0][1], w0, aA.y);
            ffma2(acc[0][2], w0, aB.x); ffma2(acc[0][3], w0, aB.y);
            ffma2(acc[1][0], w1, aA.x); ffma2(acc[1][1], w1, aA.y);
            ffma2(acc[1][2], w1, aB.x); ffma2(acc[1][3], w1, aB.y);
            ffma2(acc[2][0], w2, aA.x); ffma2(acc[2][1], w2, aA.y);
            ffma2(acc[2][2], w2, aB.x); ffma2(acc[2][3], w2, aB.y);
            ffma2(acc[3][0], w3, aA.x); ffma2(acc[3][1], w3, aA.y);
            ffma2(acc[3][2], w3, aB.x); ffma2(acc[3][3], w3, aB.y);
        }
        __syncthreads();
    }

    // Deterministic cross-slice reduction (aliases the tile smem)
    float (*sR)[32][34] = reinterpret_cast<float(*)[32][34]>(smem);
#pragma unroll
    for (int n = 0; n < 4; n++)
#pragma unroll
        for (int j = 0; j < 4; j++)
            *(unsigned long long*)&sR[slice][slot][n * 8 + j * 2] = acc[n][j];
    __syncthreads();
#pragma unroll
    for (int u = 0; u < 4; u++) {
        int oi = tid * 4 + u;
        int so = oi >> 5, ai = oi & 31;
        float sum = 0.0f;
#pragma unroll
        for (int s = 0; s < 8; s++) sum += sR[s][so][ai];
        int nL = ai >> 3, rem = ai & 7, jj = rem >> 1, hh = rem & 1;
        int b = (so >> 3) * 8 + jj * 2 + hh;
        int n = n0 + (so & 7) * 4 + nL;
        C[b * ldc + n] = sum;
    }
}

// ---------------------------------------------------------------------------
// Inverse slot map: which new-K/V row (if any) lives at each cache slot
// ---------------------------------------------------------------------------
__global__ void init_inv_kernel() {
    g_inv[blockIdx.x * 256 + threadIdx.x] = -1;
}
__global__ void scatter_inv_kernel(const int* __restrict__ smap) {
    if (threadIdx.x < BATCH) g_inv[smap[threadIdx.x]] = threadIdx.x;
}

// ---------------------------------------------------------------------------
// Per-head RMSNorm + RoPE (in place). q heads additionally folded with
// softmax scale * log2(e) so attention runs in exp2 domain.
// Grid: (40 heads [32 q + 8 k], 32 batch), 128 threads.
// ---------------------------------------------------------------------------
__global__ void normrope_kernel(const float* __restrict__ cosb,
                                const float* __restrict__ sinb,
                                const float* __restrict__ qw,
                                const float* __restrict__ kw)
{
    __shared__ float sx[HD];
    __shared__ float swr[4];
    int h = blockIdx.x;
    int b = blockIdx.y;
    int d = threadIdx.x;
    bool isq = (h < NHEAD);
    float* base = isq ? (g_q + ((size_t)b * NHEAD + h) * HD)
                      : (g_k + ((size_t)b * NKV + (h - NHEAD)) * HD);
    float x = base[d];
    float ss = x * x;
#pragma unroll
    for (int o = 16; o; o >>= 1) ss += __shfl_xor_sync(0xffffffffu, ss, o);
    if ((d & 31) == 0) swr[d >> 5] = ss;
    __syncthreads();
    float tot = swr[0] + swr[1] + swr[2] + swr[3];
    float r = rsqrtf(tot * (1.0f / HD) + 1e-6f);
    float w = isq ? qw[d] : kw[d];
    float xn = x * r * w;
    sx[d] = xn;
    __syncthreads();
    float rot = (d < HD / 2) ? -sx[d + HD / 2] : sx[d - HD / 2];
    float val = xn * cosb[b * HD + d] + rot * sinb[b * HD + d];
    if (isq) val *= 0.12752078478941477f;   // log2(e) / sqrt(128)
    base[d] = val;
}

// ---------------------------------------------------------------------------
// Split-KV attention. Block = (kvh, b), 8 warps = 8 splits of 128 positions.
// Each lane owns a d-quad; Q (4 heads x 4 dims) register-resident.
// Online softmax in log2 domain, branchless. 2-deep load pipeline.
// ---------------------------------------------------------------------------
__global__ void __launch_bounds__(256)
attn_kernel(const float* __restrict__ kc, const float* __restrict__ vc,
            const int* __restrict__ bt, const int* __restrict__ ctxl)
{
    int kvh = blockIdx.x, b = blockIdx.y;
    int w = threadIdx.x >> 5, lane = threadIdx.x & 31;
    int ctx = ctxl[b];
    int base = w * 128;
    int cnt = min(128, ctx - base);

    float qr[GRP][4];
    const float* qp = g_q + ((size_t)b * NHEAD + kvh * GRP) * HD + lane * 4;
#pragma unroll
    for (int g = 0; g < GRP; g++) {
        float4 q4 = *(const float4*)(qp + g * HD);
        qr[g][0] = q4.x; qr[g][1] = q4.y; qr[g][2] = q4.z; qr[g][3] = q4.w;
    }
    float acc[GRP][4];
    float m[GRP], l[GRP];
#pragma unroll
    for (int g = 0; g < GRP; g++) {
        m[g] = -1e30f; l[g] = 0.0f;
        acc[g][0] = acc[g][1] = acc[g][2] = acc[g][3] = 0.0f;
    }

    auto step = [&](const float4& k4, const float4& v4) {
        float s[GRP];
#pragma unroll
        for (int g = 0; g < GRP; g++)
            s[g] = fmaf(qr[g][0], k4.x, fmaf(qr[g][1], k4.y,
                   fmaf(qr[g][2], k4.z, qr[g][3] * k4.w)));
#pragma unroll
        for (int o = 16; o; o >>= 1) {
#pragma unroll
            for (int g = 0; g < GRP; g++)
                s[g] += __shfl_xor_sync(0xffffffffu, s[g], o);
        }
#pragma unroll
        for (int g = 0; g < GRP; g++) {
            float mn = fmaxf(m[g], s[g]);
            float c = exp2f(m[g] - mn);
            float e = exp2f(s[g] - mn);
            l[g] = fmaf(l[g], c, e);
            m[g] = mn;
            acc[g][0] = fmaf(acc[g][0], c, e * v4.x);
            acc[g][1] = fmaf(acc[g][1], c, e * v4.y);
            acc[g][2] = fmaf(acc[g][2], c, e * v4.z);
            acc[g][3] = fmaf(acc[g][3], c, e * v4.w);
        }
    };

    if (cnt > 0) {
        auto mkptr = [&](int p, const float*& kp, const float*& vp) {
            int pc = min(p, cnt - 1);
            int pos = base + pc;
            int bid = __ldg(bt + b * MAXBLK + (pos >> 4));
            int slotI = bid * 16 + (pos & 15);
            int j = g_inv[slotI];
            size_t co = ((size_t)slotI * NKV + kvh) * HD + lane * 4;
            size_t no = ((size_t)j * NKV + kvh) * HD + lane * 4;
            kp = (j >= 0) ? (g_k + no) : (kc + co);
            vp = (j >= 0) ? (g_v + no) : (vc + co);
        };
        const float *kp0, *vp0, *kp1, *vp1;
        mkptr(0, kp0, vp0); mkptr(1, kp1, vp1);
        float4 K0 = *(const float4*)kp0, V0 = *(const float4*)vp0;
        float4 K1 = *(const float4*)kp1, V1 = *(const float4*)vp1;
        for (int p = 0; p < cnt; p += 2) {
            float4 ka = K0, va = V0, kb = K1, vb = V1;
            mkptr(p + 2, kp0, vp0); mkptr(p + 3, kp1, vp1);
            K0 = *(const float4*)kp0; V0 = *(const float4*)vp0;
            K1 = *(const float4*)kp1; V1 = *(const float4*)vp1;
            step(ka, va);
            if (p + 1 < cnt) step(kb, vb);
        }
    }

    int pi = (b * NKV + kvh) * NSPLIT + w;
    float* pp = g_part + (size_t)pi * (GRP * HD);
#pragma unroll
    for (int g = 0; g < GRP; g++) {
        float4 o4 = make_float4(acc[g][0], acc[g][1], acc[g][2], acc[g][3]);
        *(float4*)(pp + g * HD + lane * 4) = o4;
    }
    if (lane == 0) {
#pragma unroll
        for (int g = 0; g < GRP; g++) {
            g_pm[pi * GRP + g] = m[g];
            g_pl[pi * GRP + g] = l[g];
        }
    }
}

// ---------------------------------------------------------------------------
// Merge 8 split partials per (b, kvh) head group
// ---------------------------------------------------------------------------
__global__ void combine_kernel()
{
    int kvh = blockIdx.x, b = blockIdx.y;
    int d = threadIdx.x;
    int pbase = (b * NKV + kvh) * NSPLIT;
#pragma unroll
    for (int g = 0; g < GRP; g++) {
        float mm[NSPLIT];
        float M = -1e30f;
#pragma unroll
        for (int s = 0; s < NSPLIT; s++) {
            mm[s] = g_pm[(pbase + s) * GRP + g];
            M = fmaxf(M, mm[s]);
        }
        float Lsum = 0.0f, o = 0.0f;
#pragma unroll
        for (int s = 0; s < NSPLIT; s++) {
            float wgt = exp2f(mm[s] - M);
            Lsum = fmaf(wgt, g_pl[(pbase + s) * GRP + g], Lsum);
            o = fmaf(wgt, g_part[(size_t)(pbase + s) * (GRP * HD) + g * HD + d], o);
        }
        g_attn[((size_t)b * NHEAD + kvh * GRP + g) * HD + d] = o / Lsum;
    }
}

// ---------------------------------------------------------------------------
extern "C" void kernel_launch(void* const* d_in, const int* in_sizes, int n_in,
                              void* d_out, int out_size)
{
    const float* hidden = (const float*)d_in[0];
    const float* cosb   = (const float*)d_in[1];
    const float* sinb   = (const float*)d_in[2];
    const float* kc     = (const float*)d_in[3];
    const float* vc     = (const float*)d_in[4];
    const float* Wq     = (const float*)d_in[5];
    const float* Wk     = (const float*)d_in[6];
    const float* Wv     = (const float*)d_in[7];
    const float* Wo     = (const float*)d_in[8];
    const float* qw     = (const float*)d_in[9];
    const float* kw     = (const float*)d_in[10];
    const int*   bt     = (const int*)d_in[11];
    const int*   ctxl   = (const int*)d_in[12];
    const int*   smap   = (const int*)d_in[13];
    float* out = (float*)d_out;

    float *gq, *gk, *gv, *gattn;
    cudaGetSymbolAddress((void**)&gq, g_q);
    cudaGetSymbolAddress((void**)&gk, g_k);
    cudaGetSymbolAddress((void**)&gv, g_v);
    cudaGetSymbolAddress((void**)&gattn, g_attn);

    init_inv_kernel<<<NSLOT / 256, 256>>>();
    scatter_inv_kernel<<<1, 32>>>(smap);
    gemm32<<<128, 256>>>(hidden, Wq, gq, NHEAD * HD);
    gemm32<<<32, 256>>>(hidden, Wk, gk, NKV * HD);
    gemm32<<<32, 256>>>(hidden, Wv, gv, NKV * HD);
    normrope_kernel<<<dim3(NHEAD + NKV, BATCH), HD>>>(cosb, sinb, qw, kw);
    attn_kernel<<<dim3(NKV, BATCH), 256>>>(kc, vc, bt, ctxl);
    combine_kernel<<<dim3(NKV, BATCH), HD>>>();
    gemm32<<<128, 256>>>(gattn, Wo, out, NHEAD * HD);
}

// round 2
// speedup vs baseline: 1.9253x; 1.9253x over previous
#include <cuda_runtime.h>
#include <cuda_bf16.h>
#include <cstdint>

// Problem constants
constexpr int BATCH  = 32;
constexpr int HIDDEN = 4096;
constexpr int NHEAD  = 32;
constexpr int NKV    = 8;
constexpr int HD     = 128;
constexpr int GRP    = 4;      // NHEAD / NKV
constexpr int MAXBLK = 64;
constexpr int NSLOT  = 65536;  // NUM_BLOCKS * BLOCK_SIZE
constexpr int NSPLIT = 8;      // KV splits (1 warp each, 128 positions)

// Scratch (no allocations allowed -> __device__ globals)
__device__ float g_q[BATCH * NHEAD * HD];
__device__ float g_k[BATCH * NKV * HD];
__device__ float g_v[BATCH * NKV * HD];
__device__ float g_attn[BATCH * NHEAD * HD];
__device__ float g_part[BATCH * NKV * NSPLIT * GRP * HD];
__device__ float g_pm[BATCH * NKV * NSPLIT * GRP];
__device__ float g_pl[BATCH * NKV * NSPLIT * GRP];
__device__ int   g_inv[NSLOT];

// ---------------------------------------------------------------------------
// f32x2 packed FMA helpers (2x fp32 FMA throughput vs scalar FFMA)
// ---------------------------------------------------------------------------
__device__ __forceinline__ void ffma2(unsigned long long& d, unsigned long long a,
                                      unsigned long long b) {
    asm("fma.rn.f32x2 %0, %1, %2, %0;" : "+l"(d) : "l"(a), "l"(b));
}
__device__ __forceinline__ unsigned long long pack2(float x) {
    unsigned long long r;
    asm("mov.b64 %0, {%1, %1};" : "=l"(r) : "f"(x));
    return r;
}
__device__ __forceinline__ unsigned long long pk(float lo, float hi) {
    unsigned long long r;
    asm("mov.b64 %0, {%1, %2};" : "=l"(r) : "f"(lo), "f"(hi));
    return r;
}

// ---------------------------------------------------------------------------
// GEMM body: C[32, n0..n0+32) = A[32, 4096] * W[n0..n0+32, 4096]^T
// 256 threads = 32 slots (8 n-grp x 4 b-grp) x 8 k-slices; 4n x 8b tile/thread.
// Pipeline: float4 LDG prefetch of chunk c+1 into regs while computing chunk c
// from smem; double-buffered smem, one __syncthreads per chunk.
// Smem is [k][col] with quad-swizzle col' = 4*((col>>2)^(k>>2 & 7)) + (col&3).
// ---------------------------------------------------------------------------
constexpr int CH   = 64;                // k chunk
constexpr int SSTR = 36;                // smem row stride (floats)
constexpr int TILE = CH * SSTR;         // 2304 floats per tile
constexpr int BUF  = 2 * TILE;          // sA + sW per buffer

__device__ __forceinline__ void st_swz(float* base, int kq, int col, float4 v) {
    int colp = 4 * ((col >> 2) ^ (kq & 7)) + (col & 3);
    float* p = base + (4 * kq) * SSTR + colp;
    p[0]        = v.x;
    p[SSTR]     = v.y;
    p[2 * SSTR] = v.z;
    p[3 * SSTR] = v.w;
}

__device__ __forceinline__ void gemm_body(const float* __restrict__ A,
                                          const float* __restrict__ W,
                                          float* __restrict__ C, int ldc, int n0,
                                          float* smem)
{
    const int tid   = threadIdx.x;
    const int slot  = tid & 31;
    const int slice = tid >> 5;
    const int ng    = slot & 7;
    const int bg    = slot >> 3;

    // load coords: 512 float4 per tile, 2 per thread
    const int f0 = tid, f1 = tid + 256;
    const int cA0 = f0 >> 4, kq0 = f0 & 15;
    const int cA1 = f1 >> 4, kq1 = f1 & 15;
    const float* Ap0 = A + cA0 * HIDDEN + 4 * kq0;
    const float* Ap1 = A + cA1 * HIDDEN + 4 * kq1;
    const float* Wp0 = W + (size_t)(n0 + cA0) * HIDDEN + 4 * kq0;
    const float* Wp1 = W + (size_t)(n0 + cA1) * HIDDEN + 4 * kq1;

    unsigned long long acc[4][4];
#pragma unroll
    for (int i = 0; i < 4; i++)
#pragma unroll
        for (int j = 0; j < 4; j++) acc[i][j] = 0ull;

    // prologue: chunk 0
    {
        float4 a0 = *(const float4*)Ap0;
        float4 a1 = *(const float4*)Ap1;
        float4 w0 = *(const float4*)Wp0;
        float4 w1 = *(const float4*)Wp1;
        float* sA = smem;
        float* sW = smem + TILE;
        st_swz(sA, kq0, cA0, a0);
        st_swz(sA, kq1, cA1, a1);
        st_swz(sW, kq0, cA0, w0);
        st_swz(sW, kq1, cA1, w1);
    }
    __syncthreads();

    const int NC = HIDDEN / CH;  // 64
    for (int c = 0; c < NC; c++) {
        const bool more = (c + 1 < NC);
        float4 na0, na1, nw0, nw1;
        if (more) {
            int off = (c + 1) * CH;
            na0 = *(const float4*)(Ap0 + off);
            na1 = *(const float4*)(Ap1 + off);
            nw0 = *(const float4*)(Wp0 + off);
            nw1 = *(const float4*)(Wp1 + off);
        }
        const float* sA = smem + (c & 1) * BUF;
        const float* sW = sA + TILE;
#pragma unroll
        for (int u = 0; u < 8; u++) {
            int kk = slice * 8 + u;
            int xq = (kk >> 2) & 7;
            const float* rW = sW + kk * SSTR;
            const float* rA = sA + kk * SSTR;
            float4 w4 = *(const float4*)(rW + 4 * (ng ^ xq));
            float4 aL = *(const float4*)(rA + 4 * ((2 * bg) ^ xq));
            float4 aH = *(const float4*)(rA + 4 * ((2 * bg + 1) ^ xq));
            unsigned long long ax = pk(aL.x, aL.y), ay = pk(aL.z, aL.w);
            unsigned long long bx = pk(aH.x, aH.y), by = pk(aH.z, aH.w);
            unsigned long long w0 = pack2(w4.x), w1 = pack2(w4.y);
            unsigned long long w2 = pack2(w4.z), w3 = pack2(w4.w);
            ffma2(acc[0][0], w0, ax); ffma2(acc[0][1], w0, ay);
            ffma2(acc[0][2], w0, bx); ffma2(acc[0][3], w0, by);
            ffma2(acc[1][0], w1, ax); ffma2(acc[1][1], w1, ay);
            ffma2(acc[1][2], w1, bx); ffma2(acc[1][3], w1, by);
            ffma2(acc[2][0], w2, ax); ffma2(acc[2][1], w2, ay);
            ffma2(acc[2][2], w2, bx); ffma2(acc[2][3], w2, by);
            ffma2(acc[3][0], w3, ax); ffma2(acc[3][1], w3, ay);
            ffma2(acc[3][2], w3, bx); ffma2(acc[3][3], w3, by);
        }
        if (more) {
            float* dA = smem + ((c + 1) & 1) * BUF;
            float* dW = dA + TILE;
            st_swz(dA, kq0, cA0, na0);
            st_swz(dA, kq1, cA1, na1);
            st_swz(dW, kq0, cA0, nw0);
            st_swz(dW, kq1, cA1, nw1);
        }
        __syncthreads();
    }

    // Deterministic cross-slice reduction (aliases the tile smem)
    float (*sR)[32][34] = reinterpret_cast<float(*)[32][34]>(smem);
#pragma unroll
    for (int n = 0; n < 4; n++)
#pragma unroll
        for (int j = 0; j < 4; j++)
            *(unsigned long long*)&sR[slice][slot][n * 8 + j * 2] = acc[n][j];
    __syncthreads();
#pragma unroll
    for (int u = 0; u < 4; u++) {
        int oi = tid * 4 + u;
        int so = oi >> 5, ai = oi & 31;
        float sum = 0.0f;
#pragma unroll
        for (int s = 0; s < 8; s++) sum += sR[s][so][ai];
        int nL = ai >> 3, rem = ai & 7, jj = rem >> 1, hh = rem & 1;
        int b = (so >> 3) * 8 + jj * 2 + hh;
        int n = n0 + (so & 7) * 4 + nL;
        C[b * ldc + n] = sum;
    }
}

// Fused QKV projection: grid.x = 192 (Q cols 0..4095, K 4096..5119, V 5120..6143)
__global__ void __launch_bounds__(256, 2)
qkv_gemm(const float* __restrict__ A, const float* __restrict__ Wq,
         const float* __restrict__ Wk, const float* __restrict__ Wv)
{
    __shared__ __align__(16) float smem[2 * BUF];
    int nv = blockIdx.x * 32;
    const float* W;
    float* C;
    int ldc, n0;
    if (nv < 4096)      { W = Wq; C = g_q; ldc = 4096; n0 = nv; }
    else if (nv < 5120) { W = Wk; C = g_k; ldc = 1024; n0 = nv - 4096; }
    else                { W = Wv; C = g_v; ldc = 1024; n0 = nv - 5120; }
    gemm_body(A, W, C, ldc, n0, smem);
}

// Output projection: grid.x = 128
__global__ void __launch_bounds__(256, 2)
out_gemm(const float* __restrict__ Wo, float* __restrict__ C)
{
    __shared__ __align__(16) float smem[2 * BUF];
    gemm_body(g_attn, Wo, C, 4096, blockIdx.x * 32, smem);
}

// ---------------------------------------------------------------------------
// Inverse slot map
// ---------------------------------------------------------------------------
__global__ void init_inv_kernel() {
    g_inv[blockIdx.x * 256 + threadIdx.x] = -1;
}
__global__ void scatter_inv_kernel(const int* __restrict__ smap) {
    if (threadIdx.x < BATCH) g_inv[smap[threadIdx.x]] = threadIdx.x;
}

// ---------------------------------------------------------------------------
// Per-head RMSNorm + RoPE (in place); q heads fold in scale*log2(e)
// ---------------------------------------------------------------------------
__global__ void normrope_kernel(const float* __restrict__ cosb,
                                const float* __restrict__ sinb,
                                const float* __restrict__ qw,
                                const float* __restrict__ kw)
{
    __shared__ float sx[HD];
    __shared__ float swr[4];
    int h = blockIdx.x;
    int b = blockIdx.y;
    int d = threadIdx.x;
    bool isq = (h < NHEAD);
    float* base = isq ? (g_q + ((size_t)b * NHEAD + h) * HD)
                      : (g_k + ((size_t)b * NKV + (h - NHEAD)) * HD);
    float x = base[d];
    float ss = x * x;
#pragma unroll
    for (int o = 16; o; o >>= 1) ss += __shfl_xor_sync(0xffffffffu, ss, o);
    if ((d & 31) == 0) swr[d >> 5] = ss;
    __syncthreads();
    float tot = swr[0] + swr[1] + swr[2] + swr[3];
    float r = rsqrtf(tot * (1.0f / HD) + 1e-6f);
    float w = isq ? qw[d] : kw[d];
    float xn = x * r * w;
    sx[d] = xn;
    __syncthreads();
    float rot = (d < HD / 2) ? -sx[d + HD / 2] : sx[d - HD / 2];
    float val = xn * cosb[b * HD + d] + rot * sinb[b * HD + d];
    if (isq) val *= 0.12752078478941477f;   // log2(e) / sqrt(128)
    base[d] = val;
}

// ---------------------------------------------------------------------------
// Split-KV attention. Block = (kvh, b), 8 warps = 8 splits of 128 positions.
// Phase 1 resolves block_table + inv-slot into per-position codes (smem);
// main loop runs a depth-4 float4 prefetch pipeline over K and V.
// ---------------------------------------------------------------------------
__global__ void __launch_bounds__(256)
attn_kernel(const float* __restrict__ kc, const float* __restrict__ vc,
            const int* __restrict__ bt, const int* __restrict__ ctxl)
{
    __shared__ int scode[NSPLIT][128];
    int kvh = blockIdx.x, b = blockIdx.y;
    int w = threadIdx.x >> 5, lane = threadIdx.x & 31;
    int ctx = ctxl[b];
    int base = w * 128;
    int cnt = min(128, ctx - base);

    if (cnt > 0) {
#pragma unroll
        for (int i = lane; i < 128; i += 32) {
            int pos = base + min(i, cnt - 1);
            int bid = __ldg(bt + b * MAXBLK + (pos >> 4));
            int slotI = bid * 16 + (pos & 15);
            int j = g_inv[slotI];
            scode[w][i] = (j >= 0) ? ~j : slotI;
        }
    }
    __syncwarp();

    float qr[GRP][4];
    const float* qp = g_q + ((size_t)b * NHEAD + kvh * GRP) * HD + lane * 4;
#pragma unroll
    for (int g = 0; g < GRP; g++) {
        float4 q4 = *(const float4*)(qp + g * HD);
        qr[g][0] = q4.x; qr[g][1] = q4.y; qr[g][2] = q4.z; qr[g][3] = q4.w;
    }
    float acc[GRP][4];
    float m[GRP], l[GRP];
#pragma unroll
    for (int g = 0; g < GRP; g++) {
        m[g] = -1e30f; l[g] = 0.0f;
        acc[g][0] = acc[g][1] = acc[g][2] = acc[g][3] = 0.0f;
    }

    auto step = [&](const float4& k4, const float4& v4) {
        float s[GRP];
#pragma unroll
        for (int g = 0; g < GRP; g++)
            s[g] = fmaf(qr[g][0], k4.x, fmaf(qr[g][1], k4.y,
                   fmaf(qr[g][2], k4.z, qr[g][3] * k4.w)));
#pragma unroll
        for (int o = 16; o; o >>= 1) {
#pragma unroll
            for (int g = 0; g < GRP; g++)
                s[g] += __shfl_xor_sync(0xffffffffu, s[g], o);
        }
#pragma unroll
        for (int g = 0; g < GRP; g++) {
            float mn = fmaxf(m[g], s[g]);
            float c = exp2f(m[g] - mn);
            float e = exp2f(s[g] - mn);
            l[g] = fmaf(l[g], c, e);
            m[g] = mn;
            acc[g][0] = fmaf(acc[g][0], c, e * v4.x);
            acc[g][1] = fmaf(acc[g][1], c, e * v4.y);
            acc[g][2] = fmaf(acc[g][2], c, e * v4.z);
            acc[g][3] = fmaf(acc[g][3], c, e * v4.w);
        }
    };

    if (cnt > 0) {
        auto ldkv = [&](int p, float4& K, float4& V) {
            int code = scode[w][min(p, cnt - 1)];
            const float *kb, *vb;
            size_t row;
            if (code < 0) { kb = g_k; vb = g_v; row = (size_t)(~code); }
            else          { kb = kc;  vb = vc;  row = (size_t)code; }
            size_t off = (row * NKV + kvh) * HD + lane * 4;
            K = *(const float4*)(kb + off);
            V = *(const float4*)(vb + off);
        };
        float4 Kb[4], Vb[4];
#pragma unroll
        for (int j = 0; j < 4; j++) ldkv(j, Kb[j], Vb[j]);
        for (int p = 0; p < cnt; p += 4) {
            float4 ka[4], va[4];
#pragma unroll
            for (int j = 0; j < 4; j++) { ka[j] = Kb[j]; va[j] = Vb[j]; }
#pragma unroll
            for (int j = 0; j < 4; j++) ldkv(p + 4 + j, Kb[j], Vb[j]);
#pragma unroll
            for (int j = 0; j < 4; j++)
                if (p + j < cnt) step(ka[j], va[j]);
        }
    }

    int pi = (b * NKV + kvh) * NSPLIT + w;
    float* pp = g_part + (size_t)pi * (GRP * HD);
#pragma unroll
    for (int g = 0; g < GRP; g++) {
        float4 o4 = make_float4(acc[g][0], acc[g][1], acc[g][2], acc[g][3]);
        *(float4*)(pp + g * HD + lane * 4) = o4;
    }
    if (lane == 0) {
#pragma unroll
        for (int g = 0; g < GRP; g++) {
            g_pm[pi * GRP + g] = m[g];
            g_pl[pi * GRP + g] = l[g];
        }
    }
}

// ---------------------------------------------------------------------------
// Merge 8 split partials per (b, kvh) head group
// ---------------------------------------------------------------------------
__global__ void combine_kernel()
{
    int kvh = blockIdx.x, b = blockIdx.y;
    int d = threadIdx.x;
    int pbase = (b * NKV + kvh) * NSPLIT;
#pragma unroll
    for (int g = 0; g < GRP; g++) {
        float mm[NSPLIT];
        float M = -1e30f;
#pragma unroll
        for (int s = 0; s < NSPLIT; s++) {
            mm[s] = g_pm[(pbase + s) * GRP + g];
            M = fmaxf(M, mm[s]);
        }
        float Lsum = 0.0f, o = 0.0f;
#pragma unroll
        for (int s = 0; s < NSPLIT; s++) {
            float wgt = exp2f(mm[s] - M);
            Lsum = fmaf(wgt, g_pl[(pbase + s) * GRP + g], Lsum);
            o = fmaf(wgt, g_part[(size_t)(pbase + s) * (GRP * HD) + g * HD + d], o);
        }
        g_attn[((size_t)b * NHEAD + kvh * GRP + g) * HD + d] = o / Lsum;
    }
}

// ---------------------------------------------------------------------------
extern "C" void kernel_launch(void* const* d_in, const int* in_sizes, int n_in,
                              void* d_out, int out_size)
{
    const float* hidden = (const float*)d_in[0];
    const float* cosb   = (const float*)d_in[1];
    const float* sinb   = (const float*)d_in[2];
    const float* kc     = (const float*)d_in[3];
    const float* vc     = (const float*)d_in[4];
    const float* Wq     = (const float*)d_in[5];
    const float* Wk     = (const float*)d_in[6];
    const float* Wv     = (const float*)d_in[7];
    const float* Wo     = (const float*)d_in[8];
    const float* qw     = (const float*)d_in[9];
    const float* kw     = (const float*)d_in[10];
    const int*   bt     = (const int*)d_in[11];
    const int*   ctxl   = (const int*)d_in[12];
    const int*   smap   = (const int*)d_in[13];
    float* out = (float*)d_out;

    init_inv_kernel<<<NSLOT / 256, 256>>>();
    scatter_inv_kernel<<<1, 32>>>(smap);
    qkv_gemm<<<192, 256>>>(hidden, Wq, Wk, Wv);
    normrope_kernel<<<dim3(NHEAD + NKV, BATCH), HD>>>(cosb, sinb, qw, kw);
    attn_kernel<<<dim3(NKV, BATCH), 256>>>(kc, vc, bt, ctxl);
    combine_kernel<<<dim3(NKV, BATCH), HD>>>();
    out_gemm<<<128, 256>>>(Wo, out);
}

// round 4
// speedup vs baseline: 2.2171x; 1.1516x over previous
#include <cuda_runtime.h>
#include <cuda_bf16.h>
#include <cstdint>

// Problem constants
constexpr int BATCH  = 32;
constexpr int HIDDEN = 4096;
constexpr int NHEAD  = 32;
constexpr int NKV    = 8;
constexpr int HD     = 128;
constexpr int GRP    = 4;
constexpr int MAXBLK = 64;
constexpr int NSLOT  = 65536;
constexpr int NSPLIT = 8;      // attention KV splits

constexpr int NQKV   = 6144;   // 4096 q + 1024 k + 1024 v rows
constexpr int KS_QKV = 3;      // split-K for qkv (48 tiles * 3 = 144 CTAs)
constexpr int KS_OUT = 4;      // split-K for out (32 tiles * 4 = 128 CTAs)
constexpr int CHK    = 32;     // k elements per chunk

// Scratch
__device__ float g_q[BATCH * NHEAD * HD];
__device__ float g_k[BATCH * NKV * HD];
__device__ float g_v[BATCH * NKV * HD];
__device__ float g_attn[BATCH * NHEAD * HD];
__device__ float g_part[BATCH * NKV * NSPLIT * GRP * HD];
__device__ float g_pm[BATCH * NKV * NSPLIT * GRP];
__device__ float g_pl[BATCH * NKV * NSPLIT * GRP];
__device__ int   g_inv[NSLOT];
__device__ float g_gpart[KS_QKV * NQKV * BATCH];   // [split][neuron][batch]

// ---------------------------------------------------------------------------
// helpers
// ---------------------------------------------------------------------------
__device__ __forceinline__ uint32_t smem_u32(const void* p) {
    uint32_t a;
    asm("{ .reg .u64 t; cvta.to.shared.u64 t, %1; cvt.u32.u64 %0, t; }"
        : "=r"(a) : "l"(p));
    return a;
}
__device__ __forceinline__ uint32_t swz64(uint32_t b) {
    return b ^ ((b >> 3) & 0x30u);
}
// split two fp32 into hi/lo bf16x2 (elem0 in low half)
__device__ __forceinline__ void split2(float e0, float e1, uint32_t& h, uint32_t& l) {
    asm("cvt.rn.bf16x2.f32 %0, %1, %2;" : "=r"(h) : "f"(e1), "f"(e0));
    float f0 = __uint_as_float(h << 16);
    float f1 = __uint_as_float(h & 0xFFFF0000u);
    float r0 = e0 - f0;
    float r1 = e1 - f1;
    asm("cvt.rn.bf16x2.f32 %0, %1, %2;" : "=r"(l) : "f"(r1), "f"(r0));
}
__device__ __forceinline__ void sts128(uint32_t a, const uint32_t* r) {
    asm volatile("st.shared.v4.b32 [%0], {%1, %2, %3, %4};"
                 :: "r"(a), "r"(r[0]), "r"(r[1]), "r"(r[2]), "r"(r[3]) : "memory");
}
__device__ __forceinline__ void sts64(uint32_t a, const uint32_t* r) {
    asm volatile("st.shared.v2.b32 [%0], {%1, %2};"
                 :: "r"(a), "r"(r[0]), "r"(r[1]) : "memory");
}
__device__ __forceinline__ uint32_t lds32(uint32_t a) {
    uint32_t r;
    asm volatile("ld.shared.b32 %0, [%1];" : "=r"(r) : "r"(a));
    return r;
}
__device__ __forceinline__ void ldsm4(uint32_t* r, uint32_t a) {
    asm volatile("ldmatrix.sync.aligned.m8n8.x4.shared.b16 {%0, %1, %2, %3}, [%4];"
                 : "=r"(r[0]), "=r"(r[1]), "=r"(r[2]), "=r"(r[3]) : "r"(a));
}
__device__ __forceinline__ void mma16816(float* d, const uint32_t* a,
                                         uint32_t b0, uint32_t b1) {
    asm volatile(
        "mma.sync.aligned.m16n8k16.row.col.f32.bf16.bf16.f32 "
        "{%0, %1, %2, %3}, {%4, %5, %6, %7}, {%8, %9}, {%0, %1, %2, %3};"
        : "+f"(d[0]), "+f"(d[1]), "+f"(d[2]), "+f"(d[3])
        : "r"(a[0]), "r"(a[1]), "r"(a[2]), "r"(a[3]), "r"(b0), "r"(b1));
}

// ---------------------------------------------------------------------------
// bf16 3-pass HMMA GEMM body.
// dst[(n0+m)*32 + b] = sum_k Wt[m][k] * Bact[b][k]  over chunks [ch0, ch1)
// Per-buffer smem: Wh 128x32 bf16 (SW64) | Wl | Ah 32x40 bf16 (padded) | Al
// ---------------------------------------------------------------------------
constexpr int OFF_WH = 0;
constexpr int OFF_WL = 8192;
constexpr int OFF_AH = 16384;
constexpr int OFF_AL = 16384 + 2560;
constexpr int BUFB   = 21504;

__device__ __forceinline__ void mma_body(const float* __restrict__ Bact,
                                         const float* __restrict__ Wt,
                                         float* __restrict__ dst,
                                         int n0, int ch0, int ch1,
                                         char* smem_raw)
{
    const int tid  = threadIdx.x;
    const int w    = tid >> 5;
    const int lane = tid & 31;
    const int g    = lane >> 2;
    const int tq   = lane & 3;
    const uint32_t sbase = smem_u32(smem_raw);

    // global-load coordinates
    const int wrow = tid >> 1;               // 0..127
    const int wseg = (tid & 1) * 16;         // 0 or 16 (k elems)
    const float* ap = Wt + (size_t)wrow * HIDDEN + wseg;
    const int an   = tid >> 3;               // 0..31
    const int aseg = (tid & 7) * 4;          // 0..28
    const float* bp = Bact + (size_t)an * HIDDEN + aseg;

    float4 rw[4], rb;
    auto ldc = [&](int ch) {
        const float* p = ap + ch * CHK;
        rw[0] = *(const float4*)(p);
        rw[1] = *(const float4*)(p + 4);
        rw[2] = *(const float4*)(p + 8);
        rw[3] = *(const float4*)(p + 12);
        rb = *(const float4*)(bp + ch * CHK);
    };
    auto stc = [&](uint32_t base) {
        uint32_t h[8], l[8];
#pragma unroll
        for (int i = 0; i < 4; i++) {
            split2(rw[i].x, rw[i].y, h[2 * i], l[2 * i]);
            split2(rw[i].z, rw[i].w, h[2 * i + 1], l[2 * i + 1]);
        }
        uint32_t o = (uint32_t)wrow * 64u + (uint32_t)wseg * 2u;
        sts128(base + OFF_WH + swz64(o), h);
        sts128(base + OFF_WH + swz64(o + 16), h + 4);
        sts128(base + OFF_WL + swz64(o), l);
        sts128(base + OFF_WL + swz64(o + 16), l + 4);
        uint32_t ah[2], al[2];
        split2(rb.x, rb.y, ah[0], al[0]);
        split2(rb.z, rb.w, ah[1], al[1]);
        uint32_t ao = (uint32_t)an * 80u + (uint32_t)aseg * 2u;
        sts64(base + OFF_AH + ao, ah);
        sts64(base + OFF_AL + ao, al);
    };

    float acc[4][4];
#pragma unroll
    for (int j = 0; j < 4; j++)
#pragma unroll
        for (int i = 0; i < 4; i++) acc[j][i] = 0.0f;

    // ldmatrix per-lane source row/col
    const uint32_t arow = 16u * w + ((lane >> 3) & 1) * 8 + (lane & 7);
    const uint32_t akb  = ((lane >> 4) & 1) * 16;

    auto domma = [&](uint32_t base) {
#pragma unroll
        for (int s = 0; s < 2; s++) {
            uint32_t ah[4], al[4];
            uint32_t ao = swz64(arow * 64u + akb + 32u * s);
            ldsm4(ah, base + OFF_WH + ao);
            ldsm4(al, base + OFF_WL + ao);
#pragma unroll
            for (int j = 0; j < 4; j++) {
                uint32_t ba = base + OFF_AH + (8u * j + g) * 80u + 32u * s + 4u * tq;
                uint32_t bh0 = lds32(ba), bh1 = lds32(ba + 16);
                uint32_t bl0 = lds32(ba + (OFF_AL - OFF_AH));
                uint32_t bl1 = lds32(ba + (OFF_AL - OFF_AH) + 16);
                mma16816(acc[j], ah, bh0, bh1);
                mma16816(acc[j], ah, bl0, bl1);
                mma16816(acc[j], al, bh0, bh1);
            }
        }
    };

    ldc(ch0);
    stc(sbase);
    __syncthreads();
    for (int i = ch0; i < ch1; i++) {
        int idx = i - ch0;
        if (i + 1 < ch1) ldc(i + 1);
        domma(sbase + (uint32_t)(idx & 1) * BUFB);
        if (i + 1 < ch1) stc(sbase + (uint32_t)((idx + 1) & 1) * BUFB);
        __syncthreads();
    }

    const int mbase = n0 + 16 * w;
#pragma unroll
    for (int j = 0; j < 4; j++) {
        int col = 8 * j + 2 * tq;
        *(float2*)&dst[(size_t)(mbase + g) * 32 + col] =
            make_float2(acc[j][0], acc[j][1]);
        *(float2*)&dst[(size_t)(mbase + g + 8) * 32 + col] =
            make_float2(acc[j][2], acc[j][3]);
    }
}

// QKV projection: 48 tiles x 3 K-splits = 144 CTAs
__global__ void __launch_bounds__(256)
qkv_mma(const float* __restrict__ hidden, const float* __restrict__ Wq,
        const float* __restrict__ Wk, const float* __restrict__ Wv)
{
    __shared__ __align__(128) char smem[2 * BUFB];
    int tile = blockIdx.x / KS_QKV, s = blockIdx.x % KS_QKV;
    int r0 = tile * 128;
    const float* Wt;
    if (r0 < 4096)      Wt = Wq + (size_t)r0 * HIDDEN;
    else if (r0 < 5120) Wt = Wk + (size_t)(r0 - 4096) * HIDDEN;
    else                Wt = Wv + (size_t)(r0 - 5120) * HIDDEN;
    const int cb[KS_QKV + 1] = {0, 43, 86, 128};
    mma_body(hidden, Wt, g_gpart + (size_t)s * NQKV * 32, r0, cb[s], cb[s + 1], smem);
}

// Output projection: 32 tiles x 4 K-splits = 128 CTAs
__global__ void __launch_bounds__(256)
out_mma(const float* __restrict__ Wo)
{
    __shared__ __align__(128) char smem[2 * BUFB];
    int tile = blockIdx.x >> 2, s = blockIdx.x & 3;
    mma_body(g_attn, Wo + (size_t)tile * 128 * HIDDEN,
             g_gpart + (size_t)s * HIDDEN * 32, tile * 128,
             s * 32, s * 32 + 32, smem);
}

// Reduce 4 split partials [n][b] and transpose to out[b][n]
__global__ void out_reduce(float* __restrict__ out)
{
    __shared__ float tile[32][33];
    int t = threadIdx.x;
    int n0 = blockIdx.x * 32;
    int nl = t >> 5, b = t & 31;
#pragma unroll
    for (int r = 0; r < 4; r++) {
        int n = n0 + nl + r * 8;
        float v = 0.0f;
#pragma unroll
        for (int s = 0; s < KS_OUT; s++)
            v += g_gpart[(size_t)s * HIDDEN * 32 + (size_t)n * 32 + b];
        tile[nl + r * 8][b] = v;
    }
    __syncthreads();
    int bb = t >> 3, ns = (t & 7) * 4;
    float4 o = make_float4(tile[ns][bb], tile[ns + 1][bb],
                           tile[ns + 2][bb], tile[ns + 3][bb]);
    *(float4*)&out[(size_t)bb * HIDDEN + n0 + ns] = o;
}

// ---------------------------------------------------------------------------
// Inverse slot map
// ---------------------------------------------------------------------------
__global__ void init_inv_kernel() {
    g_inv[blockIdx.x * 256 + threadIdx.x] = -1;
}
__global__ void scatter_inv_kernel(const int* __restrict__ smap) {
    if (threadIdx.x < BATCH) g_inv[smap[threadIdx.x]] = threadIdx.x;
}

// ---------------------------------------------------------------------------
// Fused split-K reduce + RMSNorm + RoPE.  grid (48, 32): h<32 q, 32..39 k,
// 40..47 v (v: plain sum).  q heads fold in scale*log2(e).
// ---------------------------------------------------------------------------
__global__ void normrope_kernel(const float* __restrict__ cosb,
                                const float* __restrict__ sinb,
                                const float* __restrict__ qw,
                                const float* __restrict__ kw)
{
    __shared__ float sx[HD];
    __shared__ float swr[4];
    int h = blockIdx.x;
    int b = blockIdx.y;
    int d = threadIdx.x;
    int n = h * HD + d;
    float x = 0.0f;
#pragma unroll
    for (int s = 0; s < KS_QKV; s++)
        x += g_gpart[(size_t)s * NQKV * 32 + (size_t)n * 32 + b];

    if (h >= 40) {  // V head: passthrough
        g_v[((size_t)b * NKV + (h - 40)) * HD + d] = x;
        return;
    }
    bool isq = (h < NHEAD);
    float ss = x * x;
#pragma unroll
    for (int o = 16; o; o >>= 1) ss += __shfl_xor_sync(0xffffffffu, ss, o);
    if ((d & 31) == 0) swr[d >> 5] = ss;
    __syncthreads();
    float tot = swr[0] + swr[1] + swr[2] + swr[3];
    float r = rsqrtf(tot * (1.0f / HD) + 1e-6f);
    float wv = isq ? qw[d] : kw[d];
    float xn = x * r * wv;
    sx[d] = xn;
    __syncthreads();
    float rot = (d < HD / 2) ? -sx[d + HD / 2] : sx[d - HD / 2];
    float val = xn * cosb[b * HD + d] + rot * sinb[b * HD + d];
    if (isq) val *= 0.12752078478941477f;   // log2(e) / sqrt(128)
    float* base = isq ? (g_q + ((size_t)b * NHEAD + h) * HD)
                      : (g_k + ((size_t)b * NKV + (h - NHEAD)) * HD);
    base[d] = val;
}

// ---------------------------------------------------------------------------
// Split-KV attention (structure from R2)
// ---------------------------------------------------------------------------
__global__ void __launch_bounds__(256)
attn_kernel(const float* __restrict__ kc, const float* __restrict__ vc,
            const int* __restrict__ bt, const int* __restrict__ ctxl)
{
    __shared__ int scode[NSPLIT][128];
    int kvh = blockIdx.x, b = blockIdx.y;
    int w = threadIdx.x >> 5, lane = threadIdx.x & 31;
    int ctx = ctxl[b];
    int base = w * 128;
    int cnt = min(128, ctx - base);

    if (cnt > 0) {
#pragma unroll
        for (int i = lane; i < 128; i += 32) {
            int pos = base + min(i, cnt - 1);
            int bid = __ldg(bt + b * MAXBLK + (pos >> 4));
            int slotI = bid * 16 + (pos & 15);
            int j = g_inv[slotI];
            scode[w][i] = (j >= 0) ? ~j : slotI;
        }
    }
    __syncwarp();

    float qr[GRP][4];
    const float* qp = g_q + ((size_t)b * NHEAD + kvh * GRP) * HD + lane * 4;
#pragma unroll
    for (int g = 0; g < GRP; g++) {
        float4 q4 = *(const float4*)(qp + g * HD);
        qr[g][0] = q4.x; qr[g][1] = q4.y; qr[g][2] = q4.z; qr[g][3] = q4.w;
    }
    float acc[GRP][4];
    float m[GRP], l[GRP];
#pragma unroll
    for (int g = 0; g < GRP; g++) {
        m[g] = -1e30f; l[g] = 0.0f;
        acc[g][0] = acc[g][1] = acc[g][2] = acc[g][3] = 0.0f;
    }

    auto step = [&](const float4& k4, const float4& v4) {
        float s[GRP];
#pragma unroll
        for (int g = 0; g < GRP; g++)
            s[g] = fmaf(qr[g][0], k4.x, fmaf(qr[g][1], k4.y,
                   fmaf(qr[g][2], k4.z, qr[g][3] * k4.w)));
#pragma unroll
        for (int o = 16; o; o >>= 1) {
#pragma unroll
            for (int g = 0; g < GRP; g++)
                s[g] += __shfl_xor_sync(0xffffffffu, s[g], o);
        }
#pragma unroll
        for (int g = 0; g < GRP; g++) {
            float mn = fmaxf(m[g], s[g]);
            float c = exp2f(m[g] - mn);
            float e = exp2f(s[g] - mn);
            l[g] = fmaf(l[g], c, e);
            m[g] = mn;
            acc[g][0] = fmaf(acc[g][0], c, e * v4.x);
            acc[g][1] = fmaf(acc[g][1], c, e * v4.y);
            acc[g][2] = fmaf(acc[g][2], c, e * v4.z);
            acc[g][3] = fmaf(acc[g][3], c, e * v4.w);
        }
    };

    if (cnt > 0) {
        auto ldkv = [&](int p, float4& K, float4& V) {
            int code = scode[w][min(p, cnt - 1)];
            const float *kb, *vb;
            size_t row;
            if (code < 0) { kb = g_k; vb = g_v; row = (size_t)(~code); }
            else          { kb = kc;  vb = vc;  row = (size_t)code; }
            size_t off = (row * NKV + kvh) * HD + lane * 4;
            K = *(const float4*)(kb + off);
            V = *(const float4*)(vb + off);
        };
        float4 Kb[4], Vb[4];
#pragma unroll
        for (int j = 0; j < 4; j++) ldkv(j, Kb[j], Vb[j]);
        for (int p = 0; p < cnt; p += 4) {
            float4 ka[4], va[4];
#pragma unroll
            for (int j = 0; j < 4; j++) { ka[j] = Kb[j]; va[j] = Vb[j]; }
#pragma unroll
            for (int j = 0; j < 4; j++) ldkv(p + 4 + j, Kb[j], Vb[j]);
#pragma unroll
            for (int j = 0; j < 4; j++)
                if (p + j < cnt) step(ka[j], va[j]);
        }
    }

    int pi = (b * NKV + kvh) * NSPLIT + w;
    float* pp = g_part + (size_t)pi * (GRP * HD);
#pragma unroll
    for (int g = 0; g < GRP; g++) {
        float4 o4 = make_float4(acc[g][0], acc[g][1], acc[g][2], acc[g][3]);
        *(float4*)(pp + g * HD + lane * 4) = o4;
    }
    if (lane == 0) {
#pragma unroll
        for (int g = 0; g < GRP; g++) {
            g_pm[pi * GRP + g] = m[g];
            g_pl[pi * GRP + g] = l[g];
        }
    }
}

__global__ void combine_kernel()
{
    int kvh = blockIdx.x, b = blockIdx.y;
    int d = threadIdx.x;
    int pbase = (b * NKV + kvh) * NSPLIT;
#pragma unroll
    for (int g = 0; g < GRP; g++) {
        float mm[NSPLIT];
        float M = -1e30f;
#pragma unroll
        for (int s = 0; s < NSPLIT; s++) {
            mm[s] = g_pm[(pbase + s) * GRP + g];
            M = fmaxf(M, mm[s]);
        }
        float Lsum = 0.0f, o = 0.0f;
#pragma unroll
        for (int s = 0; s < NSPLIT; s++) {
            float wgt = exp2f(mm[s] - M);
            Lsum = fmaf(wgt, g_pl[(pbase + s) * GRP + g], Lsum);
            o = fmaf(wgt, g_part[(size_t)(pbase + s) * (GRP * HD) + g * HD + d], o);
        }
        g_attn[((size_t)b * NHEAD + kvh * GRP + g) * HD + d] = o / Lsum;
    }
}

// ---------------------------------------------------------------------------
extern "C" void kernel_launch(void* const* d_in, const int* in_sizes, int n_in,
                              void* d_out, int out_size)
{
    const float* hidden = (const float*)d_in[0];
    const float* cosb   = (const float*)d_in[1];
    const float* sinb   = (const float*)d_in[2];
    const float* kc     = (const float*)d_in[3];
    const float* vc     = (const float*)d_in[4];
    const float* Wq     = (const float*)d_in[5];
    const float* Wk     = (const float*)d_in[6];
    const float* Wv     = (const float*)d_in[7];
    const float* Wo     = (const float*)d_in[8];
    const float* qw     = (const float*)d_in[9];
    const float* kw     = (const float*)d_in[10];
    const int*   bt     = (const int*)d_in[11];
    const int*   ctxl   = (const int*)d_in[12];
    const int*   smap   = (const int*)d_in[13];
    float* out = (float*)d_out;

    init_inv_kernel<<<NSLOT / 256, 256>>>();
    scatter_inv_kernel<<<1, 32>>>(smap);
    qkv_mma<<<48 * KS_QKV, 256>>>(hidden, Wq, Wk, Wv);
    normrope_kernel<<<dim3(48, BATCH), HD>>>(cosb, sinb, qw, kw);
    attn_kernel<<<dim3(NKV, BATCH), 256>>>(kc, vc, bt, ctxl);
    combine_kernel<<<dim3(NKV, BATCH), HD>>>();
    out_mma<<<32 * KS_OUT, 256>>>(Wo);
    out_reduce<<<HIDDEN / 32, 256>>>(out);
}